// round 12
// baseline (speedup 1.0000x reference)
#include <cuda_runtime.h>
#include <cuda_fp16.h>
#include <cstdint>
#include <cstdio>

#define B_   16
#define N1_  1024
#define N2_  1024
#define D_   1024
#define H_   16
#define DH_  64
#define MROWS (B_*N1_)   // 16384

// Scratch (allocation-free rule: __device__ globals)
__device__ __half g_Q[(size_t)B_*H_*N1_*DH_];
__device__ __half g_K[(size_t)B_*H_*N2_*DH_];
__device__ __half g_V[(size_t)B_*H_*N2_*DH_];
__device__ __half g_AO[(size_t)B_*N1_*D_];
__device__ __half g_q16[(size_t)MROWS*D_];
__device__ __half g_x16[(size_t)MROWS*D_];
__device__ __half g_Wq16[(size_t)D_*D_];
__device__ __half g_Wk16[(size_t)D_*D_];
__device__ __half g_Wv16[(size_t)D_*D_];
__device__ __half g_Wo16[(size_t)D_*D_];
__device__ unsigned char g_M[(size_t)N1_*N2_];   // canonical uint8 mask
__device__ int g_mask_is_byte;                   // dtype-detection flag

// ---------------------------------------------------------------- mask normalize
__global__ void mask_detect_kernel(const uint32_t* __restrict__ adj, int nwords) {
    uint32_t acc = 0;
    for (int i = blockIdx.x * blockDim.x + threadIdx.x; i < nwords;
         i += gridDim.x * blockDim.x)
        acc |= adj[i] & 0xFFFFFF00u;
    if (acc) atomicOr(&g_mask_is_byte, 1);
}

__global__ void mask_expand_kernel(const void* __restrict__ adj,
                                   unsigned char* __restrict__ out) {
    int i = blockIdx.x * blockDim.x + threadIdx.x;   // 4 elements per thread
    if (i >= (N1_ * N2_) / 4) return;
    uchar4 r;
    if (g_mask_is_byte) {
        uint32_t w = ((const uint32_t*)adj)[i];
        r.x = (w & 0xFFu) ? 1 : 0;
        r.y = (w & 0xFF00u) ? 1 : 0;
        r.z = (w & 0xFF0000u) ? 1 : 0;
        r.w = (w & 0xFF000000u) ? 1 : 0;
    } else {
        int4 w = ((const int4*)adj)[i];
        r.x = w.x ? 1 : 0;
        r.y = w.y ? 1 : 0;
        r.z = w.z ? 1 : 0;
        r.w = w.w ? 1 : 0;
    }
    ((uchar4*)out)[i] = r;
}

// ---------------------------------------------------------------- fp32 -> fp16
__global__ void f32_to_f16_kernel(const float* __restrict__ src,
                                  __half* __restrict__ dst, int n8) {
    int i = blockIdx.x * blockDim.x + threadIdx.x;   // 8 elements per thread
    if (i >= n8) return;
    const float4* s = (const float4*)src + i * 2;
    float4 a = s[0], b = s[1];
    __half2 h[4] = {__floats2half2_rn(a.x, a.y), __floats2half2_rn(a.z, a.w),
                    __floats2half2_rn(b.x, b.y), __floats2half2_rn(b.z, b.w)};
    *((uint4*)dst + i) = *(uint4*)h;
}

// ---------------------------------------------------------------- helpers
__device__ __forceinline__ uint32_t smem_u32(const void* p) {
    return (uint32_t)__cvta_generic_to_shared(p);
}

__device__ __forceinline__ void cp16(void* smem, const void* gmem) {
    asm volatile("cp.async.cg.shared.global [%0], [%1], 16;\n"
                 :: "r"(smem_u32(smem)), "l"(gmem));
}
__device__ __forceinline__ void cp_commit() {
    asm volatile("cp.async.commit_group;\n");
}
__device__ __forceinline__ void cp_wait0() {
    asm volatile("cp.async.wait_group 0;\n");
}
__device__ __forceinline__ void cp_wait1() {
    asm volatile("cp.async.wait_group 1;\n");
}

__device__ __forceinline__ void ldsm4(uint32_t& r0, uint32_t& r1, uint32_t& r2, uint32_t& r3,
                                      uint32_t addr) {
    asm volatile("ldmatrix.sync.aligned.m8n8.x4.shared.b16 {%0,%1,%2,%3}, [%4];\n"
                 : "=r"(r0), "=r"(r1), "=r"(r2), "=r"(r3) : "r"(addr));
}

__device__ __forceinline__ void ldsm4t(uint32_t& r0, uint32_t& r1, uint32_t& r2, uint32_t& r3,
                                       uint32_t addr) {
    asm volatile("ldmatrix.sync.aligned.m8n8.x4.trans.shared.b16 {%0,%1,%2,%3}, [%4];\n"
                 : "=r"(r0), "=r"(r1), "=r"(r2), "=r"(r3) : "r"(addr));
}

__device__ __forceinline__ void mma16816(float* c, const uint32_t* a, const uint32_t* b) {
    asm volatile(
        "mma.sync.aligned.m16n8k16.row.col.f32.f16.f16.f32 "
        "{%0,%1,%2,%3},{%4,%5,%6,%7},{%8,%9},{%0,%1,%2,%3};\n"
        : "+f"(c[0]), "+f"(c[1]), "+f"(c[2]), "+f"(c[3])
        : "r"(a[0]), "r"(a[1]), "r"(a[2]), "r"(a[3]), "r"(b[0]), "r"(b[1]));
}

__device__ __forceinline__ uint32_t packh2(float a, float b) {
    __half2 h = __floats2half2_rn(a, b);
    return *reinterpret_cast<uint32_t*>(&h);
}

// ---------------------------------------------------------------- fp16 GEMM
// C[M,N] = A[M,K] @ W[N,K]^T + bias.  M=16384, N=K=1024.
// CTA tile 128(M) x 256(N), BK=32, 2-stage cp.async pipeline.
// 256 threads = 8 warps in a 2(m) x 4(n) grid; warp tile 64x64.
// Per K16 step: 8 ldmatrix.x4 feed 32 MMAs (ratio 4.0 vs 2.7 before).
#define GPAD 40   // padded row length (halves): 80B rows, conflict-free phases
#define GSM_A_ST (128 * GPAD)            // halves per A stage
#define GSM_B_ST (256 * GPAD)            // halves per B stage
#define GSM_TOTAL ((2 * GSM_A_ST + 2 * GSM_B_ST) * 2)   // bytes = 61440

template<bool HEADSPLIT>
__global__ __launch_bounds__(256)
void gemm16_kernel(const __half* __restrict__ A, const __half* __restrict__ W,
                   const float* __restrict__ bias, void* __restrict__ C_) {
    extern __shared__ __align__(16) __half ds[];
    __half* sA = ds;                       // [2][128][GPAD]
    __half* sB = ds + 2 * GSM_A_ST;        // [2][256][GPAD]

    const int tid  = threadIdx.x;
    const int warp = tid >> 5, lane = tid & 31;
    const int m0 = blockIdx.y * 128, n0 = blockIdx.x * 256;
    const int wm = (warp >> 2) * 64, wn = (warp & 3) * 64;

    float acc[4][8][4];
#pragma unroll
    for (int i = 0; i < 4; ++i)
#pragma unroll
        for (int j = 0; j < 8; ++j)
#pragma unroll
            for (int e = 0; e < 4; ++e) acc[i][j][e] = 0.f;

    // stage loader: A 128x32 halves (2 chunks/thread), B 256x32 (4 chunks/thread)
    auto load_stage = [&](int kt, int s) {
        const int k0 = kt * 32;
#pragma unroll
        for (int i = 0; i < 2; ++i) {
            int c = tid + i * 256;            // 0..511
            int r = c >> 2, col8 = (c & 3) * 8;
            cp16(sA + s * GSM_A_ST + r * GPAD + col8,
                 A + (size_t)(m0 + r) * D_ + k0 + col8);
        }
#pragma unroll
        for (int i = 0; i < 4; ++i) {
            int c = tid + i * 256;            // 0..1023
            int r = c >> 2, col8 = (c & 3) * 8;
            cp16(sB + s * GSM_B_ST + r * GPAD + col8,
                 W + (size_t)(n0 + r) * D_ + k0 + col8);
        }
        cp_commit();
    };

    load_stage(0, 0);

    for (int kt = 0; kt < 32; ++kt) {
        cp_wait0();
        __syncthreads();
        if (kt + 1 < 32) load_stage(kt + 1, (kt + 1) & 1);

        const int s = kt & 1;
        const __half* pa = sA + s * GSM_A_ST;
        const __half* pb = sB + s * GSM_B_ST;
#pragma unroll
        for (int ks = 0; ks < 32; ks += 16) {
            uint32_t af[4][4], bf[8][2];
#pragma unroll
            for (int im = 0; im < 4; ++im) {
                int r = wm + im * 16 + (lane & 15);
                int cc = ks + (lane >> 4) * 8;
                ldsm4(af[im][0], af[im][1], af[im][2], af[im][3],
                      smem_u32(pa + r * GPAD + cc));
            }
#pragma unroll
            for (int j2 = 0; j2 < 4; ++j2) {
                int g = lane >> 3;
                int r = wn + j2 * 16 + (lane & 7) + (g >> 1) * 8;
                int cc = ks + (g & 1) * 8;
                uint32_t r0, r1, r2, r3;
                ldsm4(r0, r1, r2, r3, smem_u32(pb + r * GPAD + cc));
                bf[j2 * 2][0] = r0; bf[j2 * 2][1] = r1;
                bf[j2 * 2 + 1][0] = r2; bf[j2 * 2 + 1][1] = r3;
            }
#pragma unroll
            for (int im = 0; im < 4; ++im)
#pragma unroll
                for (int j = 0; j < 8; ++j)
                    mma16816(acc[im][j], af[im], bf[j]);
        }
    }

    // epilogue
#pragma unroll
    for (int im = 0; im < 4; ++im) {
        int r = m0 + wm + im * 16 + (lane >> 2);
#pragma unroll
        for (int j = 0; j < 8; ++j) {
            int c = n0 + wn + j * 8 + (lane & 3) * 2;
            float b0v = bias[c], b1v = bias[c + 1];
            float v00 = acc[im][j][0] + b0v, v01 = acc[im][j][1] + b1v;
            float v10 = acc[im][j][2] + b0v, v11 = acc[im][j][3] + b1v;
            if (HEADSPLIT) {
                __half* C = (__half*)C_;
                int hh = c >> 6, dh = c & 63;
                {
                    int bb = r >> 10, nn = r & 1023;
                    size_t off = (((size_t)(bb * H_ + hh)) * 1024 + nn) * 64 + dh;
                    *(__half2*)(C + off) = __floats2half2_rn(v00, v01);
                }
                {
                    int r2 = r + 8;
                    int bb = r2 >> 10, nn = r2 & 1023;
                    size_t off = (((size_t)(bb * H_ + hh)) * 1024 + nn) * 64 + dh;
                    *(__half2*)(C + off) = __floats2half2_rn(v10, v11);
                }
            } else {
                float* C = (float*)C_;
                *(float2*)(C + (size_t)r * 1024 + c) = make_float2(v00, v01);
                *(float2*)(C + (size_t)(r + 8) * 1024 + c) = make_float2(v10, v11);
            }
        }
    }
}

// ---------------------------------------------------------------- attention
// grid (N1/64, H, B), 128 threads (4 warps), 64x64 tiles, online softmax,
// 2-stage cp.async pipeline on K/V/mask. (unchanged from 780us config)
__global__ __launch_bounds__(128)
void attn_kernel(const __half* __restrict__ Qg, const __half* __restrict__ Kg,
                 const __half* __restrict__ Vg, const unsigned char* __restrict__ adj,
                 __half* __restrict__ AO) {
    __shared__ __align__(16) __half sQ[64][72];
    __shared__ __align__(16) __half sK[2][64][72];
    __shared__ __align__(16) __half sV[2][64][72];
    __shared__ __align__(16) unsigned char sM[2][64][64];

    const int tid = threadIdx.x, warp = tid >> 5, lane = tid & 31;
    const int q0 = blockIdx.x * 64, h = blockIdx.y, b = blockIdx.z;
    const float scale = 0.125f;   // DH^-0.5

    const __half* Q = Qg + ((size_t)(b * H_ + h)) * N1_ * DH_;
    const __half* K = Kg + ((size_t)(b * H_ + h)) * N2_ * DH_;
    const __half* V = Vg + ((size_t)(b * H_ + h)) * N2_ * DH_;

#pragma unroll
    for (int i = 0; i < 4; ++i) {
        int c = tid + i * 128;
        int r = c >> 3, cc = (c & 7) * 8;
        cp16(&sQ[r][cc], Q + (size_t)(q0 + r) * 64 + cc);
    }

    auto load_stage = [&](int kt, int st) {
        const int kv0 = kt * 64;
#pragma unroll
        for (int i = 0; i < 4; ++i) {
            int c = tid + i * 128;
            int r = c >> 3, cc = (c & 7) * 8;
            cp16(&sK[st][r][cc], K + (size_t)(kv0 + r) * 64 + cc);
            cp16(&sV[st][r][cc], V + (size_t)(kv0 + r) * 64 + cc);
        }
#pragma unroll
        for (int i = 0; i < 2; ++i) {
            int c = tid + i * 128;
            int r = c >> 2, cc = (c & 3) * 16;
            cp16(&sM[st][r][cc], adj + (size_t)(q0 + r) * N2_ + kv0 + cc);
        }
        cp_commit();
    };

    load_stage(0, 0);

    float accO[8][4];
#pragma unroll
    for (int j = 0; j < 8; ++j)
#pragma unroll
        for (int e = 0; e < 4; ++e) accO[j][e] = 0.f;
    float mi[2] = {-INFINITY, -INFINITY};
    float li[2] = {0.f, 0.f};

    const int rq = warp * 16 + (lane >> 2);

    for (int kt = 0; kt < 16; ++kt) {
        if (kt + 1 < 16) {
            load_stage(kt + 1, (kt + 1) & 1);
            cp_wait1();
        } else {
            cp_wait0();
        }
        __syncthreads();
        const int st = kt & 1;

        float s[8][4];
#pragma unroll
        for (int j = 0; j < 8; ++j)
#pragma unroll
            for (int e = 0; e < 4; ++e) s[j][e] = 0.f;

#pragma unroll
        for (int kk = 0; kk < 4; ++kk) {
            const int kb = kk * 16;
            uint32_t af[4];
            {
                int r = warp * 16 + (lane & 15);
                int cc = kb + (lane >> 4) * 8;
                ldsm4(af[0], af[1], af[2], af[3], smem_u32(&sQ[r][cc]));
            }
#pragma unroll
            for (int j2 = 0; j2 < 4; ++j2) {
                int g = lane >> 3;
                int r = j2 * 16 + (lane & 7) + (g >> 1) * 8;
                int cc = kb + (g & 1) * 8;
                uint32_t r0, r1, r2, r3;
                ldsm4(r0, r1, r2, r3, smem_u32(&sK[st][r][cc]));
                uint32_t bf0[2] = {r0, r1}, bf1[2] = {r2, r3};
                mma16816(s[j2 * 2],     af, bf0);
                mma16816(s[j2 * 2 + 1], af, bf1);
            }
        }

#pragma unroll
        for (int j = 0; j < 8; ++j)
#pragma unroll
            for (int e = 0; e < 4; ++e) {
                int r = rq + (e >> 1) * 8;
                int cc = j * 8 + (lane & 3) * 2 + (e & 1);
                float v = s[j][e] * scale;
                s[j][e] = sM[st][r][cc] ? v : -1e30f;
            }

        float f[2];
#pragma unroll
        for (int hh = 0; hh < 2; ++hh) {
            float m = -INFINITY;
#pragma unroll
            for (int j = 0; j < 8; ++j)
                m = fmaxf(m, fmaxf(s[j][2 * hh], s[j][2 * hh + 1]));
            m = fmaxf(m, __shfl_xor_sync(0xffffffffu, m, 1));
            m = fmaxf(m, __shfl_xor_sync(0xffffffffu, m, 2));
            float mnew = fmaxf(mi[hh], m);
            f[hh] = __expf(mi[hh] - mnew);
            mi[hh] = mnew;
        }
        float rs[2] = {0.f, 0.f};
#pragma unroll
        for (int j = 0; j < 8; ++j)
#pragma unroll
            for (int e = 0; e < 4; ++e) {
                int hh = e >> 1;
                float p = __expf(s[j][e] - mi[hh]);
                s[j][e] = p;
                rs[hh] += p;
            }
#pragma unroll
        for (int hh = 0; hh < 2; ++hh) {
            rs[hh] += __shfl_xor_sync(0xffffffffu, rs[hh], 1);
            rs[hh] += __shfl_xor_sync(0xffffffffu, rs[hh], 2);
            li[hh] = li[hh] * f[hh] + rs[hh];
        }
#pragma unroll
        for (int j = 0; j < 8; ++j)
#pragma unroll
            for (int e = 0; e < 4; ++e) accO[j][e] *= f[e >> 1];

        uint32_t pf[4][4];
#pragma unroll
        for (int t = 0; t < 4; ++t) {
            pf[t][0] = packh2(s[2 * t][0],     s[2 * t][1]);
            pf[t][1] = packh2(s[2 * t][2],     s[2 * t][3]);
            pf[t][2] = packh2(s[2 * t + 1][0], s[2 * t + 1][1]);
            pf[t][3] = packh2(s[2 * t + 1][2], s[2 * t + 1][3]);
        }

#pragma unroll
        for (int t = 0; t < 4; ++t) {
#pragma unroll
            for (int jd2 = 0; jd2 < 4; ++jd2) {
                int g = lane >> 3;
                int r = t * 16 + (lane & 7) + (g & 1) * 8;
                int cc = jd2 * 16 + (g >> 1) * 8;
                uint32_t r0, r1, r2, r3;
                ldsm4t(r0, r1, r2, r3, smem_u32(&sV[st][r][cc]));
                uint32_t bf0[2] = {r0, r1}, bf1[2] = {r2, r3};
                mma16816(accO[jd2 * 2],     pf[t], bf0);
                mma16816(accO[jd2 * 2 + 1], pf[t], bf1);
            }
        }
        __syncthreads();
    }

    float inv[2] = {1.f / li[0], 1.f / li[1]};
#pragma unroll
    for (int jd = 0; jd < 8; ++jd) {
        int dh0 = jd * 8 + (lane & 3) * 2;
#pragma unroll
        for (int hh = 0; hh < 2; ++hh) {
            int rglob = q0 + rq + hh * 8;
            __half2 v = __floats2half2_rn(accO[jd][2 * hh] * inv[hh],
                                          accO[jd][2 * hh + 1] * inv[hh]);
            *(__half2*)(AO + ((size_t)b * N1_ + rglob) * D_ + h * 64 + dh0) = v;
        }
    }
}

// ---------------------------------------------------------------- launch
extern "C" void kernel_launch(void* const* d_in, const int* in_sizes, int n_in,
                              void* d_out, int out_size) {
    const float* q  = (const float*)d_in[0];
    const float* x  = (const float*)d_in[1];
    const float* Wq = (const float*)d_in[2];
    const float* bq = (const float*)d_in[3];
    const float* Wk = (const float*)d_in[4];
    const float* bk = (const float*)d_in[5];
    const float* Wv = (const float*)d_in[6];
    const float* bv = (const float*)d_in[7];
    const float* Wo = (const float*)d_in[8];
    const float* bo = (const float*)d_in[9];
    const void*  adj = d_in[10];
    float* out = (float*)d_out;

    void *pQ, *pK, *pV, *pAO, *pM, *pFlag;
    void *pq16, *px16, *pWq, *pWk, *pWv, *pWo;
    cudaGetSymbolAddress(&pQ, g_Q);
    cudaGetSymbolAddress(&pK, g_K);
    cudaGetSymbolAddress(&pV, g_V);
    cudaGetSymbolAddress(&pAO, g_AO);
    cudaGetSymbolAddress(&pM, g_M);
    cudaGetSymbolAddress(&pFlag, g_mask_is_byte);
    cudaGetSymbolAddress(&pq16, g_q16);
    cudaGetSymbolAddress(&px16, g_x16);
    cudaGetSymbolAddress(&pWq, g_Wq16);
    cudaGetSymbolAddress(&pWk, g_Wk16);
    cudaGetSymbolAddress(&pWv, g_Wv16);
    cudaGetSymbolAddress(&pWo, g_Wo16);

    static bool attr_done = false;
    if (!attr_done) {
        cudaFuncSetAttribute(gemm16_kernel<true>,
                             cudaFuncAttributeMaxDynamicSharedMemorySize, GSM_TOTAL);
        cudaFuncSetAttribute(gemm16_kernel<false>,
                             cudaFuncAttributeMaxDynamicSharedMemorySize, GSM_TOTAL);
        attr_done = true;
    }

    // Normalize the adjacency mask to uint8 regardless of wire dtype.
    cudaMemsetAsync(pFlag, 0, sizeof(int));
    mask_detect_kernel<<<256, 256>>>((const uint32_t*)adj, (N1_ * N2_) / 4);
    mask_expand_kernel<<<(N1_ * N2_ / 4 + 255) / 256, 256>>>(adj, (unsigned char*)pM);

    // fp32 -> fp16 pre-conversion (activations + weights)
    const int big8 = MROWS * D_ / 8, w8 = D_ * D_ / 8;
    f32_to_f16_kernel<<<(big8 + 255) / 256, 256>>>(q,  (__half*)pq16, big8);
    f32_to_f16_kernel<<<(big8 + 255) / 256, 256>>>(x,  (__half*)px16, big8);
    f32_to_f16_kernel<<<(w8 + 255) / 256, 256>>>(Wq, (__half*)pWq, w8);
    f32_to_f16_kernel<<<(w8 + 255) / 256, 256>>>(Wk, (__half*)pWk, w8);
    f32_to_f16_kernel<<<(w8 + 255) / 256, 256>>>(Wv, (__half*)pWv, w8);
    f32_to_f16_kernel<<<(w8 + 255) / 256, 256>>>(Wo, (__half*)pWo, w8);

    dim3 gg(D_ / 256, MROWS / 128);
    gemm16_kernel<true><<<gg, 256, GSM_TOTAL>>>((const __half*)pq16, (const __half*)pWq, bq, pQ);
    gemm16_kernel<true><<<gg, 256, GSM_TOTAL>>>((const __half*)px16, (const __half*)pWk, bk, pK);
    gemm16_kernel<true><<<gg, 256, GSM_TOTAL>>>((const __half*)px16, (const __half*)pWv, bv, pV);
    attn_kernel<<<dim3(N1_ / 64, H_, B_), 128>>>((const __half*)pQ, (const __half*)pK,
                                                 (const __half*)pV,
                                                 (const unsigned char*)pM, (__half*)pAO);
    gemm16_kernel<false><<<gg, 256, GSM_TOTAL>>>((const __half*)pAO, (const __half*)pWo, bo, out);
}

// round 13
// speedup vs baseline: 1.1999x; 1.1999x over previous
#include <cuda_runtime.h>
#include <cuda_fp16.h>
#include <cstdint>
#include <cstdio>

#define B_   16
#define N1_  1024
#define N2_  1024
#define D_   1024
#define H_   16
#define DH_  64
#define MROWS (B_*N1_)   // 16384

// Scratch (allocation-free rule: __device__ globals)
__device__ __half g_Q[(size_t)B_*H_*N1_*DH_];
__device__ __half g_K[(size_t)B_*H_*N2_*DH_];
__device__ __half g_V[(size_t)B_*H_*N2_*DH_];
__device__ __half g_AO[(size_t)B_*N1_*D_];
__device__ __half g_q16[(size_t)MROWS*D_];
__device__ __half g_x16[(size_t)MROWS*D_];
__device__ __half g_Wq16[(size_t)D_*D_];
__device__ __half g_Wk16[(size_t)D_*D_];
__device__ __half g_Wv16[(size_t)D_*D_];
__device__ __half g_Wo16[(size_t)D_*D_];
__device__ unsigned char g_M[(size_t)N1_*N2_];   // canonical uint8 mask
__device__ int g_mask_is_byte;                   // dtype-detection flag

// ---------------------------------------------------------------- mask normalize
__global__ void mask_detect_kernel(const uint32_t* __restrict__ adj, int nwords) {
    uint32_t acc = 0;
    for (int i = blockIdx.x * blockDim.x + threadIdx.x; i < nwords;
         i += gridDim.x * blockDim.x)
        acc |= adj[i] & 0xFFFFFF00u;
    if (acc) atomicOr(&g_mask_is_byte, 1);
}

__global__ void mask_expand_kernel(const void* __restrict__ adj,
                                   unsigned char* __restrict__ out) {
    int i = blockIdx.x * blockDim.x + threadIdx.x;   // 4 elements per thread
    if (i >= (N1_ * N2_) / 4) return;
    uchar4 r;
    if (g_mask_is_byte) {
        uint32_t w = ((const uint32_t*)adj)[i];
        r.x = (w & 0xFFu) ? 1 : 0;
        r.y = (w & 0xFF00u) ? 1 : 0;
        r.z = (w & 0xFF0000u) ? 1 : 0;
        r.w = (w & 0xFF000000u) ? 1 : 0;
    } else {
        int4 w = ((const int4*)adj)[i];
        r.x = w.x ? 1 : 0;
        r.y = w.y ? 1 : 0;
        r.z = w.z ? 1 : 0;
        r.w = w.w ? 1 : 0;
    }
    ((uchar4*)out)[i] = r;
}

// ---------------------------------------------------------------- fp32 -> fp16
__device__ __forceinline__ void conv8(const float* __restrict__ src,
                                      __half* __restrict__ dst, int i) {
    const float4* s = (const float4*)src + i * 2;
    float4 a = s[0], b = s[1];
    __half2 h[4] = {__floats2half2_rn(a.x, a.y), __floats2half2_rn(a.z, a.w),
                    __floats2half2_rn(b.x, b.y), __floats2half2_rn(b.z, b.w)};
    *((uint4*)dst + i) = *(uint4*)h;
}

// two big activations in one launch (blockIdx.y selects)
__global__ void f32_to_f16_x2_kernel(const float* __restrict__ s0, __half* __restrict__ d0,
                                     const float* __restrict__ s1, __half* __restrict__ d1,
                                     int n8) {
    int i = blockIdx.x * blockDim.x + threadIdx.x;
    if (i >= n8) return;
    if (blockIdx.y == 0) conv8(s0, d0, i);
    else                 conv8(s1, d1, i);
}

// four weight matrices in one launch (blockIdx.y selects)
__global__ void f32_to_f16_x4_kernel(const float* __restrict__ s0, __half* __restrict__ d0,
                                     const float* __restrict__ s1, __half* __restrict__ d1,
                                     const float* __restrict__ s2, __half* __restrict__ d2,
                                     const float* __restrict__ s3, __half* __restrict__ d3,
                                     int n8) {
    int i = blockIdx.x * blockDim.x + threadIdx.x;
    if (i >= n8) return;
    switch (blockIdx.y) {
        case 0: conv8(s0, d0, i); break;
        case 1: conv8(s1, d1, i); break;
        case 2: conv8(s2, d2, i); break;
        default: conv8(s3, d3, i); break;
    }
}

// ---------------------------------------------------------------- helpers
__device__ __forceinline__ uint32_t smem_u32(const void* p) {
    return (uint32_t)__cvta_generic_to_shared(p);
}

__device__ __forceinline__ void cp16(void* smem, const void* gmem) {
    asm volatile("cp.async.cg.shared.global [%0], [%1], 16;\n"
                 :: "r"(smem_u32(smem)), "l"(gmem));
}
__device__ __forceinline__ void cp_commit() {
    asm volatile("cp.async.commit_group;\n");
}
__device__ __forceinline__ void cp_wait0() {
    asm volatile("cp.async.wait_group 0;\n");
}
__device__ __forceinline__ void cp_wait1() {
    asm volatile("cp.async.wait_group 1;\n");
}

__device__ __forceinline__ void ldsm4(uint32_t& r0, uint32_t& r1, uint32_t& r2, uint32_t& r3,
                                      uint32_t addr) {
    asm volatile("ldmatrix.sync.aligned.m8n8.x4.shared.b16 {%0,%1,%2,%3}, [%4];\n"
                 : "=r"(r0), "=r"(r1), "=r"(r2), "=r"(r3) : "r"(addr));
}

__device__ __forceinline__ void ldsm4t(uint32_t& r0, uint32_t& r1, uint32_t& r2, uint32_t& r3,
                                       uint32_t addr) {
    asm volatile("ldmatrix.sync.aligned.m8n8.x4.trans.shared.b16 {%0,%1,%2,%3}, [%4];\n"
                 : "=r"(r0), "=r"(r1), "=r"(r2), "=r"(r3) : "r"(addr));
}

__device__ __forceinline__ void mma16816(float* c, const uint32_t* a, const uint32_t* b) {
    asm volatile(
        "mma.sync.aligned.m16n8k16.row.col.f32.f16.f16.f32 "
        "{%0,%1,%2,%3},{%4,%5,%6,%7},{%8,%9},{%0,%1,%2,%3};\n"
        : "+f"(c[0]), "+f"(c[1]), "+f"(c[2]), "+f"(c[3])
        : "r"(a[0]), "r"(a[1]), "r"(a[2]), "r"(a[3]), "r"(b[0]), "r"(b[1]));
}

__device__ __forceinline__ uint32_t packh2(float a, float b) {
    __half2 h = __floats2half2_rn(a, b);
    return *reinterpret_cast<uint32_t*>(&h);
}

// ---------------------------------------------------------------- fp16 GEMM core
// (inner loop identical to the 780us Round-9 kernel: BM=128, BN=128, BK=32, 2-stage)
#define GPAD 40   // padded row length (halves): 80B rows, conflict-free phases

template<bool HEADSPLIT>
__device__ __forceinline__ void gemm16_body(const __half* __restrict__ A,
                                            const __half* __restrict__ W,
                                            const float* __restrict__ bias,
                                            void* __restrict__ C_,
                                            __half (*sA)[128][GPAD],
                                            __half (*sB)[128][GPAD]) {
    const int tid  = threadIdx.x;
    const int warp = tid >> 5, lane = tid & 31;
    const int m0 = blockIdx.y * 128, n0 = blockIdx.x * 128;
    const int wm = (warp >> 2) * 64, wn = (warp & 3) * 32;

    float acc[4][4][4];
#pragma unroll
    for (int i = 0; i < 4; ++i)
#pragma unroll
        for (int j = 0; j < 4; ++j)
#pragma unroll
            for (int e = 0; e < 4; ++e) acc[i][j][e] = 0.f;

    auto load_stage = [&](int kt, int s) {
        const int k0 = kt * 32;
#pragma unroll
        for (int i = 0; i < 2; ++i) {
            int c = tid + i * 256;
            int r = c >> 2, col8 = (c & 3) * 8;
            cp16(&sA[s][r][col8], A + (size_t)(m0 + r) * D_ + k0 + col8);
            cp16(&sB[s][r][col8], W + (size_t)(n0 + r) * D_ + k0 + col8);
        }
        cp_commit();
    };

    load_stage(0, 0);

    for (int kt = 0; kt < 32; ++kt) {
        cp_wait0();
        __syncthreads();
        if (kt + 1 < 32) load_stage(kt + 1, (kt + 1) & 1);

        const int s = kt & 1;
#pragma unroll
        for (int ks = 0; ks < 32; ks += 16) {
            uint32_t af[4][4], bf[4][2];
#pragma unroll
            for (int im = 0; im < 4; ++im) {
                int r = wm + im * 16 + (lane & 15);
                int cc = ks + (lane >> 4) * 8;
                ldsm4(af[im][0], af[im][1], af[im][2], af[im][3],
                      smem_u32(&sA[s][r][cc]));
            }
#pragma unroll
            for (int j2 = 0; j2 < 2; ++j2) {
                int g = lane >> 3;
                int r = wn + j2 * 16 + (lane & 7) + (g >> 1) * 8;
                int cc = ks + (g & 1) * 8;
                uint32_t r0, r1, r2, r3;
                ldsm4(r0, r1, r2, r3, smem_u32(&sB[s][r][cc]));
                bf[j2 * 2][0] = r0; bf[j2 * 2][1] = r1;
                bf[j2 * 2 + 1][0] = r2; bf[j2 * 2 + 1][1] = r3;
            }
#pragma unroll
            for (int im = 0; im < 4; ++im)
#pragma unroll
                for (int j = 0; j < 4; ++j)
                    mma16816(acc[im][j], af[im], bf[j]);
        }
    }

    // epilogue
#pragma unroll
    for (int im = 0; im < 4; ++im) {
        int r = m0 + wm + im * 16 + (lane >> 2);
#pragma unroll
        for (int j = 0; j < 4; ++j) {
            int c = n0 + wn + j * 8 + (lane & 3) * 2;
            float b0v = bias[c], b1v = bias[c + 1];
            float v00 = acc[im][j][0] + b0v, v01 = acc[im][j][1] + b1v;
            float v10 = acc[im][j][2] + b0v, v11 = acc[im][j][3] + b1v;
            if (HEADSPLIT) {
                __half* C = (__half*)C_;
                int hh = c >> 6, dh = c & 63;
                {
                    int bb = r >> 10, nn = r & 1023;
                    size_t off = (((size_t)(bb * H_ + hh)) * 1024 + nn) * 64 + dh;
                    *(__half2*)(C + off) = __floats2half2_rn(v00, v01);
                }
                {
                    int r2 = r + 8;
                    int bb = r2 >> 10, nn = r2 & 1023;
                    size_t off = (((size_t)(bb * H_ + hh)) * 1024 + nn) * 64 + dh;
                    *(__half2*)(C + off) = __floats2half2_rn(v10, v11);
                }
            } else {
                float* C = (float*)C_;
                *(float2*)(C + (size_t)r * 1024 + c) = make_float2(v00, v01);
                *(float2*)(C + (size_t)(r + 8) * 1024 + c) = make_float2(v10, v11);
            }
        }
    }
}

// Fused Q/K/V projections: grid.z selects {A, W, bias, C}; one big launch
// (3072 CTAs) amortizes the wave tail that 3 x 1024-CTA launches expose.
__global__ __launch_bounds__(256)
void gemm16_qkv_kernel(const __half* __restrict__ Aq, const __half* __restrict__ Ax,
                       const __half* __restrict__ Wq, const __half* __restrict__ Wk,
                       const __half* __restrict__ Wv,
                       const float* __restrict__ bq, const float* __restrict__ bk,
                       const float* __restrict__ bv,
                       __half* __restrict__ Cq, __half* __restrict__ Ck,
                       __half* __restrict__ Cv) {
    __shared__ __align__(16) __half sA[2][128][GPAD];
    __shared__ __align__(16) __half sB[2][128][GPAD];
    const __half* A; const __half* W; const float* bias; __half* C;
    if (blockIdx.z == 0)      { A = Aq; W = Wq; bias = bq; C = Cq; }
    else if (blockIdx.z == 1) { A = Ax; W = Wk; bias = bk; C = Ck; }
    else                      { A = Ax; W = Wv; bias = bv; C = Cv; }
    gemm16_body<true>(A, W, bias, C, sA, sB);
}

__global__ __launch_bounds__(256)
void gemm16_out_kernel(const __half* __restrict__ A, const __half* __restrict__ W,
                       const float* __restrict__ bias, float* __restrict__ C) {
    __shared__ __align__(16) __half sA[2][128][GPAD];
    __shared__ __align__(16) __half sB[2][128][GPAD];
    gemm16_body<false>(A, W, bias, C, sA, sB);
}

// ---------------------------------------------------------------- attention
// grid (N1/64, H, B), 128 threads (4 warps), 64x64 tiles, online softmax,
// 2-stage cp.async pipeline on K/V/mask. (unchanged from 780us config)
__global__ __launch_bounds__(128)
void attn_kernel(const __half* __restrict__ Qg, const __half* __restrict__ Kg,
                 const __half* __restrict__ Vg, const unsigned char* __restrict__ adj,
                 __half* __restrict__ AO) {
    __shared__ __align__(16) __half sQ[64][72];
    __shared__ __align__(16) __half sK[2][64][72];
    __shared__ __align__(16) __half sV[2][64][72];
    __shared__ __align__(16) unsigned char sM[2][64][64];

    const int tid = threadIdx.x, warp = tid >> 5, lane = tid & 31;
    const int q0 = blockIdx.x * 64, h = blockIdx.y, b = blockIdx.z;
    const float scale = 0.125f;   // DH^-0.5

    const __half* Q = Qg + ((size_t)(b * H_ + h)) * N1_ * DH_;
    const __half* K = Kg + ((size_t)(b * H_ + h)) * N2_ * DH_;
    const __half* V = Vg + ((size_t)(b * H_ + h)) * N2_ * DH_;

#pragma unroll
    for (int i = 0; i < 4; ++i) {
        int c = tid + i * 128;
        int r = c >> 3, cc = (c & 7) * 8;
        cp16(&sQ[r][cc], Q + (size_t)(q0 + r) * 64 + cc);
    }

    auto load_stage = [&](int kt, int st) {
        const int kv0 = kt * 64;
#pragma unroll
        for (int i = 0; i < 4; ++i) {
            int c = tid + i * 128;
            int r = c >> 3, cc = (c & 7) * 8;
            cp16(&sK[st][r][cc], K + (size_t)(kv0 + r) * 64 + cc);
            cp16(&sV[st][r][cc], V + (size_t)(kv0 + r) * 64 + cc);
        }
#pragma unroll
        for (int i = 0; i < 2; ++i) {
            int c = tid + i * 128;
            int r = c >> 2, cc = (c & 3) * 16;
            cp16(&sM[st][r][cc], adj + (size_t)(q0 + r) * N2_ + kv0 + cc);
        }
        cp_commit();
    };

    load_stage(0, 0);

    float accO[8][4];
#pragma unroll
    for (int j = 0; j < 8; ++j)
#pragma unroll
        for (int e = 0; e < 4; ++e) accO[j][e] = 0.f;
    float mi[2] = {-INFINITY, -INFINITY};
    float li[2] = {0.f, 0.f};

    const int rq = warp * 16 + (lane >> 2);

    for (int kt = 0; kt < 16; ++kt) {
        if (kt + 1 < 16) {
            load_stage(kt + 1, (kt + 1) & 1);
            cp_wait1();
        } else {
            cp_wait0();
        }
        __syncthreads();
        const int st = kt & 1;

        float s[8][4];
#pragma unroll
        for (int j = 0; j < 8; ++j)
#pragma unroll
            for (int e = 0; e < 4; ++e) s[j][e] = 0.f;

#pragma unroll
        for (int kk = 0; kk < 4; ++kk) {
            const int kb = kk * 16;
            uint32_t af[4];
            {
                int r = warp * 16 + (lane & 15);
                int cc = kb + (lane >> 4) * 8;
                ldsm4(af[0], af[1], af[2], af[3], smem_u32(&sQ[r][cc]));
            }
#pragma unroll
            for (int j2 = 0; j2 < 4; ++j2) {
                int g = lane >> 3;
                int r = j2 * 16 + (lane & 7) + (g >> 1) * 8;
                int cc = kb + (g & 1) * 8;
                uint32_t r0, r1, r2, r3;
                ldsm4(r0, r1, r2, r3, smem_u32(&sK[st][r][cc]));
                uint32_t bf0[2] = {r0, r1}, bf1[2] = {r2, r3};
                mma16816(s[j2 * 2],     af, bf0);
                mma16816(s[j2 * 2 + 1], af, bf1);
            }
        }

#pragma unroll
        for (int j = 0; j < 8; ++j)
#pragma unroll
            for (int e = 0; e < 4; ++e) {
                int r = rq + (e >> 1) * 8;
                int cc = j * 8 + (lane & 3) * 2 + (e & 1);
                float v = s[j][e] * scale;
                s[j][e] = sM[st][r][cc] ? v : -1e30f;
            }

        float f[2];
#pragma unroll
        for (int hh = 0; hh < 2; ++hh) {
            float m = -INFINITY;
#pragma unroll
            for (int j = 0; j < 8; ++j)
                m = fmaxf(m, fmaxf(s[j][2 * hh], s[j][2 * hh + 1]));
            m = fmaxf(m, __shfl_xor_sync(0xffffffffu, m, 1));
            m = fmaxf(m, __shfl_xor_sync(0xffffffffu, m, 2));
            float mnew = fmaxf(mi[hh], m);
            f[hh] = __expf(mi[hh] - mnew);
            mi[hh] = mnew;
        }
        float rs[2] = {0.f, 0.f};
#pragma unroll
        for (int j = 0; j < 8; ++j)
#pragma unroll
            for (int e = 0; e < 4; ++e) {
                int hh = e >> 1;
                float p = __expf(s[j][e] - mi[hh]);
                s[j][e] = p;
                rs[hh] += p;
            }
#pragma unroll
        for (int hh = 0; hh < 2; ++hh) {
            rs[hh] += __shfl_xor_sync(0xffffffffu, rs[hh], 1);
            rs[hh] += __shfl_xor_sync(0xffffffffu, rs[hh], 2);
            li[hh] = li[hh] * f[hh] + rs[hh];
        }
#pragma unroll
        for (int j = 0; j < 8; ++j)
#pragma unroll
            for (int e = 0; e < 4; ++e) accO[j][e] *= f[e >> 1];

        uint32_t pf[4][4];
#pragma unroll
        for (int t = 0; t < 4; ++t) {
            pf[t][0] = packh2(s[2 * t][0],     s[2 * t][1]);
            pf[t][1] = packh2(s[2 * t][2],     s[2 * t][3]);
            pf[t][2] = packh2(s[2 * t + 1][0], s[2 * t + 1][1]);
            pf[t][3] = packh2(s[2 * t + 1][2], s[2 * t + 1][3]);
        }

#pragma unroll
        for (int t = 0; t < 4; ++t) {
#pragma unroll
            for (int jd2 = 0; jd2 < 4; ++jd2) {
                int g = lane >> 3;
                int r = t * 16 + (lane & 7) + (g & 1) * 8;
                int cc = jd2 * 16 + (g >> 1) * 8;
                uint32_t r0, r1, r2, r3;
                ldsm4t(r0, r1, r2, r3, smem_u32(&sV[st][r][cc]));
                uint32_t bf0[2] = {r0, r1}, bf1[2] = {r2, r3};
                mma16816(accO[jd2 * 2],     pf[t], bf0);
                mma16816(accO[jd2 * 2 + 1], pf[t], bf1);
            }
        }
        __syncthreads();
    }

    float inv[2] = {1.f / li[0], 1.f / li[1]};
#pragma unroll
    for (int jd = 0; jd < 8; ++jd) {
        int dh0 = jd * 8 + (lane & 3) * 2;
#pragma unroll
        for (int hh = 0; hh < 2; ++hh) {
            int rglob = q0 + rq + hh * 8;
            __half2 v = __floats2half2_rn(accO[jd][2 * hh] * inv[hh],
                                          accO[jd][2 * hh + 1] * inv[hh]);
            *(__half2*)(AO + ((size_t)b * N1_ + rglob) * D_ + h * 64 + dh0) = v;
        }
    }
}

// ---------------------------------------------------------------- launch
extern "C" void kernel_launch(void* const* d_in, const int* in_sizes, int n_in,
                              void* d_out, int out_size) {
    const float* q  = (const float*)d_in[0];
    const float* x  = (const float*)d_in[1];
    const float* Wq = (const float*)d_in[2];
    const float* bq = (const float*)d_in[3];
    const float* Wk = (const float*)d_in[4];
    const float* bk = (const float*)d_in[5];
    const float* Wv = (const float*)d_in[6];
    const float* bv = (const float*)d_in[7];
    const float* Wo = (const float*)d_in[8];
    const float* bo = (const float*)d_in[9];
    const void*  adj = d_in[10];
    float* out = (float*)d_out;

    void *pQ, *pK, *pV, *pAO, *pM, *pFlag;
    void *pq16, *px16, *pWq, *pWk, *pWv, *pWo;
    cudaGetSymbolAddress(&pQ, g_Q);
    cudaGetSymbolAddress(&pK, g_K);
    cudaGetSymbolAddress(&pV, g_V);
    cudaGetSymbolAddress(&pAO, g_AO);
    cudaGetSymbolAddress(&pM, g_M);
    cudaGetSymbolAddress(&pFlag, g_mask_is_byte);
    cudaGetSymbolAddress(&pq16, g_q16);
    cudaGetSymbolAddress(&px16, g_x16);
    cudaGetSymbolAddress(&pWq, g_Wq16);
    cudaGetSymbolAddress(&pWk, g_Wk16);
    cudaGetSymbolAddress(&pWv, g_Wv16);
    cudaGetSymbolAddress(&pWo, g_Wo16);

    // Normalize the adjacency mask to uint8 regardless of wire dtype.
    cudaMemsetAsync(pFlag, 0, sizeof(int));
    mask_detect_kernel<<<256, 256>>>((const uint32_t*)adj, (N1_ * N2_) / 4);
    mask_expand_kernel<<<(N1_ * N2_ / 4 + 255) / 256, 256>>>(adj, (unsigned char*)pM);

    // fp32 -> fp16 pre-conversion: 2 launches (activations, weights)
    const int big8 = MROWS * D_ / 8, w8 = D_ * D_ / 8;
    f32_to_f16_x2_kernel<<<dim3((big8 + 255) / 256, 2), 256>>>(
        q, (__half*)pq16, x, (__half*)px16, big8);
    f32_to_f16_x4_kernel<<<dim3((w8 + 255) / 256, 4), 256>>>(
        Wq, (__half*)pWq, Wk, (__half*)pWk, Wv, (__half*)pWv, Wo, (__half*)pWo, w8);

    // fused Q/K/V projections: one launch, 3072 CTAs
    gemm16_qkv_kernel<<<dim3(D_ / 128, MROWS / 128, 3), 256>>>(
        (const __half*)pq16, (const __half*)px16,
        (const __half*)pWq, (const __half*)pWk, (const __half*)pWv,
        bq, bk, bv,
        (__half*)pQ, (__half*)pK, (__half*)pV);

    attn_kernel<<<dim3(N1_ / 64, H_, B_), 128>>>((const __half*)pQ, (const __half*)pK,
                                                 (const __half*)pV,
                                                 (const unsigned char*)pM, (__half*)pAO);

    gemm16_out_kernel<<<dim3(D_ / 128, MROWS / 128), 256>>>(
        (const __half*)pAO, (const __half*)pWo, bo, out);
}

// round 14
// speedup vs baseline: 1.2230x; 1.0193x over previous
#include <cuda_runtime.h>
#include <cuda_fp16.h>
#include <cstdint>
#include <cstdio>

#define B_   16
#define N1_  1024
#define N2_  1024
#define D_   1024
#define H_   16
#define DH_  64
#define MROWS (B_*N1_)   // 16384
#define NW_  (N2_/64)    // 16 mask words per row

// Scratch (allocation-free rule: __device__ globals)
__device__ __half g_Q[(size_t)B_*H_*N1_*DH_];
__device__ __half g_K[(size_t)B_*H_*N2_*DH_];
__device__ __half g_V[(size_t)B_*H_*N2_*DH_];
__device__ __half g_AO[(size_t)B_*N1_*D_];
__device__ __half g_q16[(size_t)MROWS*D_];
__device__ __half g_x16[(size_t)MROWS*D_];
__device__ __half g_Wq16[(size_t)D_*D_];
__device__ __half g_Wk16[(size_t)D_*D_];
__device__ __half g_Wv16[(size_t)D_*D_];
__device__ __half g_Wo16[(size_t)D_*D_];
__device__ unsigned long long g_Mb[(size_t)N1_*NW_];  // bit-packed mask
__device__ int g_mask_is_byte;                        // dtype-detection flag

// ---------------------------------------------------------------- mask normalize
__global__ void mask_detect_kernel(const uint32_t* __restrict__ adj, int nwords) {
    uint32_t acc = 0;
    for (int i = blockIdx.x * blockDim.x + threadIdx.x; i < nwords;
         i += gridDim.x * blockDim.x)
        acc |= adj[i] & 0xFFFFFF00u;
    if (acc) atomicOr(&g_mask_is_byte, 1);
}

// pack 64 adjacent columns into one uint64 (bit c = adj[row][col0+c] != 0)
__global__ void mask_pack_kernel(const void* __restrict__ adj,
                                 unsigned long long* __restrict__ out) {
    int w = blockIdx.x * blockDim.x + threadIdx.x;
    if (w >= N1_ * NW_) return;
    int row = w >> 4, col0 = (w & 15) * 64;
    unsigned long long bits = 0;
    if (g_mask_is_byte) {
        const uint32_t* a = (const uint32_t*)((const unsigned char*)adj +
                                              (size_t)row * N2_ + col0);
#pragma unroll
        for (int i = 0; i < 16; ++i) {          // 16 x 4 bytes
            uint32_t v = a[i];
            if (v & 0xFFu)        bits |= 1ull << (i * 4 + 0);
            if (v & 0xFF00u)      bits |= 1ull << (i * 4 + 1);
            if (v & 0xFF0000u)    bits |= 1ull << (i * 4 + 2);
            if (v & 0xFF000000u)  bits |= 1ull << (i * 4 + 3);
        }
    } else {
        const int4* a = (const int4*)((const int*)adj + (size_t)row * N2_ + col0);
#pragma unroll
        for (int i = 0; i < 16; ++i) {          // 16 x 4 ints
            int4 v = a[i];
            if (v.x) bits |= 1ull << (i * 4 + 0);
            if (v.y) bits |= 1ull << (i * 4 + 1);
            if (v.z) bits |= 1ull << (i * 4 + 2);
            if (v.w) bits |= 1ull << (i * 4 + 3);
        }
    }
    out[w] = bits;
}

// ---------------------------------------------------------------- fp32 -> fp16
__device__ __forceinline__ void conv8(const float* __restrict__ src,
                                      __half* __restrict__ dst, int i) {
    const float4* s = (const float4*)src + i * 2;
    float4 a = s[0], b = s[1];
    __half2 h[4] = {__floats2half2_rn(a.x, a.y), __floats2half2_rn(a.z, a.w),
                    __floats2half2_rn(b.x, b.y), __floats2half2_rn(b.z, b.w)};
    *((uint4*)dst + i) = *(uint4*)h;
}

__global__ void f32_to_f16_x2_kernel(const float* __restrict__ s0, __half* __restrict__ d0,
                                     const float* __restrict__ s1, __half* __restrict__ d1,
                                     int n8) {
    int i = blockIdx.x * blockDim.x + threadIdx.x;
    if (i >= n8) return;
    if (blockIdx.y == 0) conv8(s0, d0, i);
    else                 conv8(s1, d1, i);
}

__global__ void f32_to_f16_x4_kernel(const float* __restrict__ s0, __half* __restrict__ d0,
                                     const float* __restrict__ s1, __half* __restrict__ d1,
                                     const float* __restrict__ s2, __half* __restrict__ d2,
                                     const float* __restrict__ s3, __half* __restrict__ d3,
                                     int n8) {
    int i = blockIdx.x * blockDim.x + threadIdx.x;
    if (i >= n8) return;
    switch (blockIdx.y) {
        case 0: conv8(s0, d0, i); break;
        case 1: conv8(s1, d1, i); break;
        case 2: conv8(s2, d2, i); break;
        default: conv8(s3, d3, i); break;
    }
}

// ---------------------------------------------------------------- helpers
__device__ __forceinline__ uint32_t smem_u32(const void* p) {
    return (uint32_t)__cvta_generic_to_shared(p);
}

__device__ __forceinline__ void cp16(void* smem, const void* gmem) {
    asm volatile("cp.async.cg.shared.global [%0], [%1], 16;\n"
                 :: "r"(smem_u32(smem)), "l"(gmem));
}
__device__ __forceinline__ void cp8(void* smem, const void* gmem) {
    asm volatile("cp.async.ca.shared.global [%0], [%1], 8;\n"
                 :: "r"(smem_u32(smem)), "l"(gmem));
}
__device__ __forceinline__ void cp_commit() {
    asm volatile("cp.async.commit_group;\n");
}
__device__ __forceinline__ void cp_wait0() {
    asm volatile("cp.async.wait_group 0;\n");
}
__device__ __forceinline__ void cp_wait1() {
    asm volatile("cp.async.wait_group 1;\n");
}

__device__ __forceinline__ void ldsm4(uint32_t& r0, uint32_t& r1, uint32_t& r2, uint32_t& r3,
                                      uint32_t addr) {
    asm volatile("ldmatrix.sync.aligned.m8n8.x4.shared.b16 {%0,%1,%2,%3}, [%4];\n"
                 : "=r"(r0), "=r"(r1), "=r"(r2), "=r"(r3) : "r"(addr));
}

__device__ __forceinline__ void ldsm4t(uint32_t& r0, uint32_t& r1, uint32_t& r2, uint32_t& r3,
                                       uint32_t addr) {
    asm volatile("ldmatrix.sync.aligned.m8n8.x4.trans.shared.b16 {%0,%1,%2,%3}, [%4];\n"
                 : "=r"(r0), "=r"(r1), "=r"(r2), "=r"(r3) : "r"(addr));
}

__device__ __forceinline__ void mma16816(float* c, const uint32_t* a, const uint32_t* b) {
    asm volatile(
        "mma.sync.aligned.m16n8k16.row.col.f32.f16.f16.f32 "
        "{%0,%1,%2,%3},{%4,%5,%6,%7},{%8,%9},{%0,%1,%2,%3};\n"
        : "+f"(c[0]), "+f"(c[1]), "+f"(c[2]), "+f"(c[3])
        : "r"(a[0]), "r"(a[1]), "r"(a[2]), "r"(a[3]), "r"(b[0]), "r"(b[1]));
}

__device__ __forceinline__ uint32_t packh2(float a, float b) {
    __half2 h = __floats2half2_rn(a, b);
    return *reinterpret_cast<uint32_t*>(&h);
}

// ---------------------------------------------------------------- fp16 GEMM core
// (inner loop identical to the 758us Round-13 kernel)
#define GPAD 40   // padded row length (halves): 80B rows, conflict-free phases

template<bool HEADSPLIT>
__device__ __forceinline__ void gemm16_body(const __half* __restrict__ A,
                                            const __half* __restrict__ W,
                                            const float* __restrict__ bias,
                                            void* __restrict__ C_,
                                            __half (*sA)[128][GPAD],
                                            __half (*sB)[128][GPAD]) {
    const int tid  = threadIdx.x;
    const int warp = tid >> 5, lane = tid & 31;
    const int m0 = blockIdx.y * 128, n0 = blockIdx.x * 128;
    const int wm = (warp >> 2) * 64, wn = (warp & 3) * 32;

    float acc[4][4][4];
#pragma unroll
    for (int i = 0; i < 4; ++i)
#pragma unroll
        for (int j = 0; j < 4; ++j)
#pragma unroll
            for (int e = 0; e < 4; ++e) acc[i][j][e] = 0.f;

    auto load_stage = [&](int kt, int s) {
        const int k0 = kt * 32;
#pragma unroll
        for (int i = 0; i < 2; ++i) {
            int c = tid + i * 256;
            int r = c >> 2, col8 = (c & 3) * 8;
            cp16(&sA[s][r][col8], A + (size_t)(m0 + r) * D_ + k0 + col8);
            cp16(&sB[s][r][col8], W + (size_t)(n0 + r) * D_ + k0 + col8);
        }
        cp_commit();
    };

    load_stage(0, 0);

    for (int kt = 0; kt < 32; ++kt) {
        cp_wait0();
        __syncthreads();
        if (kt + 1 < 32) load_stage(kt + 1, (kt + 1) & 1);

        const int s = kt & 1;
#pragma unroll
        for (int ks = 0; ks < 32; ks += 16) {
            uint32_t af[4][4], bf[4][2];
#pragma unroll
            for (int im = 0; im < 4; ++im) {
                int r = wm + im * 16 + (lane & 15);
                int cc = ks + (lane >> 4) * 8;
                ldsm4(af[im][0], af[im][1], af[im][2], af[im][3],
                      smem_u32(&sA[s][r][cc]));
            }
#pragma unroll
            for (int j2 = 0; j2 < 2; ++j2) {
                int g = lane >> 3;
                int r = wn + j2 * 16 + (lane & 7) + (g >> 1) * 8;
                int cc = ks + (g & 1) * 8;
                uint32_t r0, r1, r2, r3;
                ldsm4(r0, r1, r2, r3, smem_u32(&sB[s][r][cc]));
                bf[j2 * 2][0] = r0; bf[j2 * 2][1] = r1;
                bf[j2 * 2 + 1][0] = r2; bf[j2 * 2 + 1][1] = r3;
            }
#pragma unroll
            for (int im = 0; im < 4; ++im)
#pragma unroll
                for (int j = 0; j < 4; ++j)
                    mma16816(acc[im][j], af[im], bf[j]);
        }
    }

    // epilogue
#pragma unroll
    for (int im = 0; im < 4; ++im) {
        int r = m0 + wm + im * 16 + (lane >> 2);
#pragma unroll
        for (int j = 0; j < 4; ++j) {
            int c = n0 + wn + j * 8 + (lane & 3) * 2;
            float b0v = bias[c], b1v = bias[c + 1];
            float v00 = acc[im][j][0] + b0v, v01 = acc[im][j][1] + b1v;
            float v10 = acc[im][j][2] + b0v, v11 = acc[im][j][3] + b1v;
            if (HEADSPLIT) {
                __half* C = (__half*)C_;
                int hh = c >> 6, dh = c & 63;
                {
                    int bb = r >> 10, nn = r & 1023;
                    size_t off = (((size_t)(bb * H_ + hh)) * 1024 + nn) * 64 + dh;
                    *(__half2*)(C + off) = __floats2half2_rn(v00, v01);
                }
                {
                    int r2 = r + 8;
                    int bb = r2 >> 10, nn = r2 & 1023;
                    size_t off = (((size_t)(bb * H_ + hh)) * 1024 + nn) * 64 + dh;
                    *(__half2*)(C + off) = __floats2half2_rn(v10, v11);
                }
            } else {
                float* C = (float*)C_;
                *(float2*)(C + (size_t)r * 1024 + c) = make_float2(v00, v01);
                *(float2*)(C + (size_t)(r + 8) * 1024 + c) = make_float2(v10, v11);
            }
        }
    }
}

// Fused Q/K/V projections: grid.z selects {A, W, bias, C}
__global__ __launch_bounds__(256)
void gemm16_qkv_kernel(const __half* __restrict__ Aq, const __half* __restrict__ Ax,
                       const __half* __restrict__ Wq, const __half* __restrict__ Wk,
                       const __half* __restrict__ Wv,
                       const float* __restrict__ bq, const float* __restrict__ bk,
                       const float* __restrict__ bv,
                       __half* __restrict__ Cq, __half* __restrict__ Ck,
                       __half* __restrict__ Cv) {
    __shared__ __align__(16) __half sA[2][128][GPAD];
    __shared__ __align__(16) __half sB[2][128][GPAD];
    const __half* A; const __half* W; const float* bias; __half* C;
    if (blockIdx.z == 0)      { A = Aq; W = Wq; bias = bq; C = Cq; }
    else if (blockIdx.z == 1) { A = Ax; W = Wk; bias = bk; C = Ck; }
    else                      { A = Ax; W = Wv; bias = bv; C = Cv; }
    gemm16_body<true>(A, W, bias, C, sA, sB);
}

__global__ __launch_bounds__(256)
void gemm16_out_kernel(const __half* __restrict__ A, const __half* __restrict__ W,
                       const float* __restrict__ bias, float* __restrict__ C) {
    __shared__ __align__(16) __half sA[2][128][GPAD];
    __shared__ __align__(16) __half sB[2][128][GPAD];
    gemm16_body<false>(A, W, bias, C, sA, sB);
}

// ---------------------------------------------------------------- attention
// grid (N1/64, H, B), 128 threads (4 warps), 64x64 tiles, online softmax,
// 2-stage cp.async pipeline on K/V, bit-packed mask (2 x LDS.64 per tile
// instead of 32 byte-LDS per thread).
__global__ __launch_bounds__(128)
void attn_kernel(const __half* __restrict__ Qg, const __half* __restrict__ Kg,
                 const __half* __restrict__ Vg,
                 const unsigned long long* __restrict__ Mb,
                 __half* __restrict__ AO) {
    __shared__ __align__(16) __half sQ[64][72];
    __shared__ __align__(16) __half sK[2][64][72];
    __shared__ __align__(16) __half sV[2][64][72];
    __shared__ __align__(16) unsigned long long sMb[2][64];

    const int tid = threadIdx.x, warp = tid >> 5, lane = tid & 31;
    const int q0 = blockIdx.x * 64, h = blockIdx.y, b = blockIdx.z;
    const float scale = 0.125f;   // DH^-0.5

    const __half* Q = Qg + ((size_t)(b * H_ + h)) * N1_ * DH_;
    const __half* K = Kg + ((size_t)(b * H_ + h)) * N2_ * DH_;
    const __half* V = Vg + ((size_t)(b * H_ + h)) * N2_ * DH_;

#pragma unroll
    for (int i = 0; i < 4; ++i) {
        int c = tid + i * 128;
        int r = c >> 3, cc = (c & 7) * 8;
        cp16(&sQ[r][cc], Q + (size_t)(q0 + r) * 64 + cc);
    }

    auto load_stage = [&](int kt, int st) {
        const int kv0 = kt * 64;
#pragma unroll
        for (int i = 0; i < 4; ++i) {
            int c = tid + i * 128;
            int r = c >> 3, cc = (c & 7) * 8;
            cp16(&sK[st][r][cc], K + (size_t)(kv0 + r) * 64 + cc);
            cp16(&sV[st][r][cc], V + (size_t)(kv0 + r) * 64 + cc);
        }
        if (tid < 64)   // one 8B mask word per q-row for this 64-col tile
            cp8(&sMb[st][tid], Mb + (size_t)(q0 + tid) * NW_ + kt);
        cp_commit();
    };

    load_stage(0, 0);

    float accO[8][4];
#pragma unroll
    for (int j = 0; j < 8; ++j)
#pragma unroll
        for (int e = 0; e < 4; ++e) accO[j][e] = 0.f;
    float mi[2] = {-INFINITY, -INFINITY};
    float li[2] = {0.f, 0.f};

    const int rq = warp * 16 + (lane >> 2);

    for (int kt = 0; kt < 16; ++kt) {
        if (kt + 1 < 16) {
            load_stage(kt + 1, (kt + 1) & 1);
            cp_wait1();
        } else {
            cp_wait0();
        }
        __syncthreads();
        const int st = kt & 1;

        float s[8][4];
#pragma unroll
        for (int j = 0; j < 8; ++j)
#pragma unroll
            for (int e = 0; e < 4; ++e) s[j][e] = 0.f;

#pragma unroll
        for (int kk = 0; kk < 4; ++kk) {
            const int kb = kk * 16;
            uint32_t af[4];
            {
                int r = warp * 16 + (lane & 15);
                int cc = kb + (lane >> 4) * 8;
                ldsm4(af[0], af[1], af[2], af[3], smem_u32(&sQ[r][cc]));
            }
#pragma unroll
            for (int j2 = 0; j2 < 4; ++j2) {
                int g = lane >> 3;
                int r = j2 * 16 + (lane & 7) + (g >> 1) * 8;
                int cc = kb + (g & 1) * 8;
                uint32_t r0, r1, r2, r3;
                ldsm4(r0, r1, r2, r3, smem_u32(&sK[st][r][cc]));
                uint32_t bf0[2] = {r0, r1}, bf1[2] = {r2, r3};
                mma16816(s[j2 * 2],     af, bf0);
                mma16816(s[j2 * 2 + 1], af, bf1);
            }
        }

        // scale + mask via bit tests (row words broadcast across the quad)
        const unsigned long long w0 = sMb[st][rq];
        const unsigned long long w1 = sMb[st][rq + 8];
        const int cbase = (lane & 3) * 2;
#pragma unroll
        for (int j = 0; j < 8; ++j) {
            unsigned int b0 = (unsigned int)(w0 >> (j * 8 + cbase));
            unsigned int b1 = (unsigned int)(w1 >> (j * 8 + cbase));
            s[j][0] = (b0 & 1u) ? s[j][0] * scale : -1e30f;
            s[j][1] = (b0 & 2u) ? s[j][1] * scale : -1e30f;
            s[j][2] = (b1 & 1u) ? s[j][2] * scale : -1e30f;
            s[j][3] = (b1 & 2u) ? s[j][3] * scale : -1e30f;
        }

        float f[2];
#pragma unroll
        for (int hh = 0; hh < 2; ++hh) {
            float m = -INFINITY;
#pragma unroll
            for (int j = 0; j < 8; ++j)
                m = fmaxf(m, fmaxf(s[j][2 * hh], s[j][2 * hh + 1]));
            m = fmaxf(m, __shfl_xor_sync(0xffffffffu, m, 1));
            m = fmaxf(m, __shfl_xor_sync(0xffffffffu, m, 2));
            float mnew = fmaxf(mi[hh], m);
            f[hh] = __expf(mi[hh] - mnew);
            mi[hh] = mnew;
        }
        float rs[2] = {0.f, 0.f};
#pragma unroll
        for (int j = 0; j < 8; ++j)
#pragma unroll
            for (int e = 0; e < 4; ++e) {
                int hh = e >> 1;
                float p = __expf(s[j][e] - mi[hh]);
                s[j][e] = p;
                rs[hh] += p;
            }
#pragma unroll
        for (int hh = 0; hh < 2; ++hh) {
            rs[hh] += __shfl_xor_sync(0xffffffffu, rs[hh], 1);
            rs[hh] += __shfl_xor_sync(0xffffffffu, rs[hh], 2);
            li[hh] = li[hh] * f[hh] + rs[hh];
        }
#pragma unroll
        for (int j = 0; j < 8; ++j)
#pragma unroll
            for (int e = 0; e < 4; ++e) accO[j][e] *= f[e >> 1];

        uint32_t pf[4][4];
#pragma unroll
        for (int t = 0; t < 4; ++t) {
            pf[t][0] = packh2(s[2 * t][0],     s[2 * t][1]);
            pf[t][1] = packh2(s[2 * t][2],     s[2 * t][3]);
            pf[t][2] = packh2(s[2 * t + 1][0], s[2 * t + 1][1]);
            pf[t][3] = packh2(s[2 * t + 1][2], s[2 * t + 1][3]);
        }

#pragma unroll
        for (int t = 0; t < 4; ++t) {
#pragma unroll
            for (int jd2 = 0; jd2 < 4; ++jd2) {
                int g = lane >> 3;
                int r = t * 16 + (lane & 7) + (g & 1) * 8;
                int cc = jd2 * 16 + (g >> 1) * 8;
                uint32_t r0, r1, r2, r3;
                ldsm4t(r0, r1, r2, r3, smem_u32(&sV[st][r][cc]));
                uint32_t bf0[2] = {r0, r1}, bf1[2] = {r2, r3};
                mma16816(accO[jd2 * 2],     pf[t], bf0);
                mma16816(accO[jd2 * 2 + 1], pf[t], bf1);
            }
        }
        __syncthreads();
    }

    float inv[2] = {1.f / li[0], 1.f / li[1]};
#pragma unroll
    for (int jd = 0; jd < 8; ++jd) {
        int dh0 = jd * 8 + (lane & 3) * 2;
#pragma unroll
        for (int hh = 0; hh < 2; ++hh) {
            int rglob = q0 + rq + hh * 8;
            __half2 v = __floats2half2_rn(accO[jd][2 * hh] * inv[hh],
                                          accO[jd][2 * hh + 1] * inv[hh]);
            *(__half2*)(AO + ((size_t)b * N1_ + rglob) * D_ + h * 64 + dh0) = v;
        }
    }
}

// ---------------------------------------------------------------- launch
extern "C" void kernel_launch(void* const* d_in, const int* in_sizes, int n_in,
                              void* d_out, int out_size) {
    const float* q  = (const float*)d_in[0];
    const float* x  = (const float*)d_in[1];
    const float* Wq = (const float*)d_in[2];
    const float* bq = (const float*)d_in[3];
    const float* Wk = (const float*)d_in[4];
    const float* bk = (const float*)d_in[5];
    const float* Wv = (const float*)d_in[6];
    const float* bv = (const float*)d_in[7];
    const float* Wo = (const float*)d_in[8];
    const float* bo = (const float*)d_in[9];
    const void*  adj = d_in[10];
    float* out = (float*)d_out;

    void *pQ, *pK, *pV, *pAO, *pMb, *pFlag;
    void *pq16, *px16, *pWq, *pWk, *pWv, *pWo;
    cudaGetSymbolAddress(&pQ, g_Q);
    cudaGetSymbolAddress(&pK, g_K);
    cudaGetSymbolAddress(&pV, g_V);
    cudaGetSymbolAddress(&pAO, g_AO);
    cudaGetSymbolAddress(&pMb, g_Mb);
    cudaGetSymbolAddress(&pFlag, g_mask_is_byte);
    cudaGetSymbolAddress(&pq16, g_q16);
    cudaGetSymbolAddress(&px16, g_x16);
    cudaGetSymbolAddress(&pWq, g_Wq16);
    cudaGetSymbolAddress(&pWk, g_Wk16);
    cudaGetSymbolAddress(&pWv, g_Wv16);
    cudaGetSymbolAddress(&pWo, g_Wo16);

    // Normalize the adjacency mask to packed bits regardless of wire dtype.
    cudaMemsetAsync(pFlag, 0, sizeof(int));
    mask_detect_kernel<<<256, 256>>>((const uint32_t*)adj, (N1_ * N2_) / 4);
    mask_pack_kernel<<<(N1_ * NW_ + 255) / 256, 256>>>(adj, (unsigned long long*)pMb);

    // fp32 -> fp16 pre-conversion: 2 launches (activations, weights)
    const int big8 = MROWS * D_ / 8, w8 = D_ * D_ / 8;
    f32_to_f16_x2_kernel<<<dim3((big8 + 255) / 256, 2), 256>>>(
        q, (__half*)pq16, x, (__half*)px16, big8);
    f32_to_f16_x4_kernel<<<dim3((w8 + 255) / 256, 4), 256>>>(
        Wq, (__half*)pWq, Wk, (__half*)pWk, Wv, (__half*)pWv, Wo, (__half*)pWo, w8);

    // fused Q/K/V projections: one launch, 3072 CTAs
    gemm16_qkv_kernel<<<dim3(D_ / 128, MROWS / 128, 3), 256>>>(
        (const __half*)pq16, (const __half*)px16,
        (const __half*)pWq, (const __half*)pWk, (const __half*)pWv,
        bq, bk, bv,
        (__half*)pQ, (__half*)pK, (__half*)pV);

    attn_kernel<<<dim3(N1_ / 64, H_, B_), 128>>>((const __half*)pQ, (const __half*)pK,
                                                 (const __half*)pV,
                                                 (const unsigned long long*)pMb,
                                                 (__half*)pAO);

    gemm16_out_kernel<<<dim3(D_ / 128, MROWS / 128), 256>>>(
        (const __half*)pAO, (const __half*)pWo, bo, out);
}